// round 17
// baseline (speedup 1.0000x reference)
#include <cuda_runtime.h>
#include <cuda_fp16.h>

typedef unsigned int u32;
typedef unsigned long long u64;

#define NAB 36

// Scratch (__device__ global; no allocation allowed)
__device__ __align__(256) __half g_W[NAB * 64 * 64];  // W fp16 [ab][co][ci]

__device__ __forceinline__ u32 smem_u32(const void* p) {
    u32 a;
    asm("{ .reg .u64 t; cvta.to.shared.u64 t, %1; cvt.u32.u64 %0, t; }" : "=r"(a) : "l"(p));
    return a;
}
__device__ __forceinline__ void cp16(u32 dst, const void* src) {
    asm volatile("cp.async.cg.shared.global [%0], [%1], 16;" :: "r"(dst), "l"(src) : "memory");
}
__device__ __forceinline__ void ldmx4(u32* r, u32 addr) {
    asm volatile("ldmatrix.sync.aligned.m8n8.x4.shared.b16 {%0,%1,%2,%3}, [%4];"
        : "=r"(r[0]), "=r"(r[1]), "=r"(r[2]), "=r"(r[3]) : "r"(addr));
}
__device__ __forceinline__ void mma16f(float* d, const u32* a, const u32* b) {
    asm volatile(
        "mma.sync.aligned.m16n8k16.row.col.f32.f16.f16.f32 "
        "{%0,%1,%2,%3}, {%4,%5,%6,%7}, {%8,%9}, {%0,%1,%2,%3};"
        : "+f"(d[0]), "+f"(d[1]), "+f"(d[2]), "+f"(d[3])
        : "r"(a[0]), "r"(a[1]), "r"(a[2]), "r"(a[3]), "r"(b[0]), "r"(b[1]));
}

// ---- packed fp32x2 helpers ----
__device__ __forceinline__ u64 pk2(float x) {
    u64 r; asm("mov.b64 %0, {%1, %1};" : "=l"(r) : "f"(x)); return r;
}
__device__ __forceinline__ u64 fma2_(u64 a, u64 b, u64 c) {
    u64 r; asm("fma.rn.f32x2 %0, %1, %2, %3;" : "=l"(r) : "l"(a), "l"(b), "l"(c)); return r;
}
__device__ __forceinline__ u64 add2_(u64 a, u64 b) {
    u64 r; asm("add.rn.f32x2 %0, %1, %2;" : "=l"(r) : "l"(a), "l"(b)); return r;
}
__device__ __forceinline__ u64 sub2_(u64 a, u64 b) {
    u64 r; asm("sub.rn.f32x2 %0, %1, %2;" : "=l"(r) : "l"(a), "l"(b)); return r;
}
__device__ __forceinline__ u32 cvt2h(u64 v) {
    float lo, hi; u32 r;
    asm("mov.b64 {%0, %1}, %2;" : "=f"(lo), "=f"(hi) : "l"(v));
    asm("cvt.rn.f16x2.f32 %0, %1, %2;" : "=r"(r) : "f"(hi), "f"(lo));
    return r;   // {lo half = lo, hi half = hi}
}

// ---------------------------------------------------------------------------
// K1: weight prep  weight[co][ci][ab] -> fp16 [ab][co][ci]
// ---------------------------------------------------------------------------
__global__ __launch_bounds__(256) void wt_kernel(const float* __restrict__ w) {
    int idx = blockIdx.x * 256 + threadIdx.x;      // ab*4096 + co*64 + ci
    if (idx >= NAB * 64 * 64) return;
    int ci = idx & 63;
    int co = (idx >> 6) & 63;
    int ab = idx >> 12;
    g_W[idx] = __float2half_rn(w[(co * 64 + ci) * 36 + ab]);
}

// ---------------------------------------------------------------------------
// K2: MEGA kernel, m-tile 16 (grid 1024), 256 threads = 8 warps, warp tile
// 16m x 8co.  Phase 0: input transform into smem V_s; x staged [pos][ci]
// (pitch 66), transform computed 2-channels-wide in packed fp32x2 by 128
// threads, packed f16x2 stores.  Phase 1: GEMM + output transform, zero
// block barriers, compile-time stage schedule (identical to R16 winner).
// SMEM 111456 B -> 2 CTAs/SM (regs capped via launch_bounds).
// ---------------------------------------------------------------------------
#define VS_PLANE  2304                        // bytes per V plane = 16 rows * 144
#define OVL_OFF   (36 * VS_PLANE)             // 82944
#define WBUF_ST   1152                        // per-stage: 8 rows * 144 B
#define NSTW      3
#define WBUF_WARP (NSTW * WBUF_ST)            // 3456 per warp (8 warps = 27648)
#define SX_PITCH  66                          // floats per pos (8B-aligned pairs)
#define SX_BYTES  (108 * SX_PITCH * 4)        // 28512
#define GSM_TOTAL (OVL_OFF + SX_BYTES)        // 111456 bytes

__global__ __launch_bounds__(256, 2) void mega_kernel(const float* __restrict__ x,
                                                      const float* __restrict__ bias,
                                                      float* __restrict__ y) {
    extern __shared__ char sm[];
    float* sx = (float*)(sm + OVL_OFF);       // [pos 0..107][ci 0..63], pitch 66
    const int tid = threadIdx.x;
    const int m0 = blockIdx.x * 16;
    const int n = m0 >> 10;
    const int p = (m0 >> 5) & 31;
    const int q0 = m0 & 31;                   // 0 or 16
    const u32 sb0 = smem_u32(sm);

    // per-thread decomposition for strength-reduced staging indices
    const int tid18 = tid % 18;
    const int tidu  = tid / 18;
    const int tidu6 = tidu % 6;
    const int tiduq = tidu / 6;
    const int B0p = (tidu6 * 18 + tid18) * SX_PITCH + tiduq;  // sx base [pos][ci]
    const int A0  = tiduq * 16384 + tidu6 * 128 + tid18;      // x offset base

    // packed constants (phase 0)
    const u64 c4  = pk2(4.0f);
    const u64 cm4 = pk2(-4.0f);
    const u64 cm5 = pk2(-5.0f);
    const u64 c2  = pk2(2.0f);
    const u64 cm2 = pk2(-2.0f);

    // ================= phase 0: input transform into V_s =================
    for (int qc = 0; qc < 4; qc++) {
        const int h0 = p * 4 - 1;
        const int w0 = (q0 + qc * 4) * 4 - 1;
        const float* xb = x + (size_t)(n * 64) * 16384 + h0 * 128 + w0;
        const bool safe = (p > 0) && (p < 31) &&
                          !(q0 == 0 && qc == 0) && !(q0 == 16 && qc == 3);
        if (safe) {
#pragma unroll
            for (int k = 0; k < 27; k++) {
                const int C0 = (256 * k) % 18;
                const int C1 = (256 * k) / 18;
                const int R1 = C1 % 6, Q1 = C1 / 6;
                int p1 = (tid18 >= 18 - C0) ? 1 : 0;
                int e  = tidu6 + R1 + p1;
                int p2 = (e >= 6) ? 1 : 0;
                int sxoff = B0p + ((R1 * 18 + C0) * SX_PITCH + Q1)
                          + p2 * (1 - 108 * SX_PITCH);
                int xoff  = A0 + (Q1 * 16384 + R1 * 128 + C0) + p1 * 110 + p2 * 15616;
                sx[sxoff] = xb[xoff];
            }
        } else {
#pragma unroll
            for (int k = 0; k < 27; k++) {
                const int C0 = (256 * k) % 18;
                const int C1 = (256 * k) / 18;
                const int R1 = C1 % 6, Q1 = C1 / 6;
                int p1 = (tid18 >= 18 - C0) ? 1 : 0;
                int e  = tidu6 + R1 + p1;
                int p2 = (e >= 6) ? 1 : 0;
                int sxoff = B0p + ((R1 * 18 + C0) * SX_PITCH + Q1)
                          + p2 * (1 - 108 * SX_PITCH);
                int xoff  = A0 + (Q1 * 16384 + R1 * 128 + C0) + p1 * 110 + p2 * 15616;
                int wl = tid18 + C0 - 18 * p1;
                int hl = e - 6 * p2;
                int gh = h0 + hl, gw = w0 + wl;
                float val = 0.0f;
                if ((unsigned)gh < 128u && (unsigned)gw < 128u) val = xb[xoff];
                sx[sxoff] = val;
            }
        }
        __syncthreads();

        if (tid < 128) {
            const int ci2 = tid & 31;         // ci pair: (2*ci2, 2*ci2+1)
            const int qt  = tid >> 5;         // 0..3
            const int ql  = qc * 4 + qt;      // local V row 0..15

            // load d packed over the ci pair
            u64 d[6][6];
#pragma unroll
            for (int i = 0; i < 6; i++)
#pragma unroll
                for (int j = 0; j < 6; j++)
                    d[i][j] = *(const u64*)&sx[(i * 18 + qt * 4 + j) * SX_PITCH + 2 * ci2];

            // t = BT * d  (packed)
            u64 t[6][6];
#pragma unroll
            for (int j = 0; j < 6; j++) {
                t[0][j] = fma2_(c4, d[0][j], fma2_(cm5, d[2][j], d[4][j]));
                t[1][j] = fma2_(cm4, add2_(d[1][j], d[2][j]), add2_(d[3][j], d[4][j]));
                t[2][j] = fma2_(c4, sub2_(d[1][j], d[2][j]), sub2_(d[4][j], d[3][j]));
                u64 uu = sub2_(d[3][j], d[1][j]);
                u64 ss = sub2_(d[4][j], d[2][j]);
                t[3][j] = fma2_(c2, uu, ss);
                t[4][j] = fma2_(cm2, uu, ss);
                t[5][j] = fma2_(c4, d[1][j], fma2_(cm5, d[3][j], d[5][j]));
            }

            // v = t * BT^T (packed), convert to f16x2, store
            char* vdst = sm + ql * 144 + ci2 * 4;
#pragma unroll
            for (int a = 0; a < 6; a++) {
                u64 v0 = fma2_(c4, t[a][0], fma2_(cm5, t[a][2], t[a][4]));
                u64 v1 = fma2_(cm4, add2_(t[a][1], t[a][2]), add2_(t[a][3], t[a][4]));
                u64 v2 = fma2_(c4, sub2_(t[a][1], t[a][2]), sub2_(t[a][4], t[a][3]));
                u64 uu = sub2_(t[a][3], t[a][1]);
                u64 ss = sub2_(t[a][4], t[a][2]);
                u64 v3 = fma2_(c2, uu, ss);
                u64 v4 = fma2_(cm2, uu, ss);
                u64 v5 = fma2_(c4, t[a][1], fma2_(cm5, t[a][3], t[a][5]));
                *(u32*)(vdst + (a * 6 + 0) * VS_PLANE) = cvt2h(v0);
                *(u32*)(vdst + (a * 6 + 1) * VS_PLANE) = cvt2h(v1);
                *(u32*)(vdst + (a * 6 + 2) * VS_PLANE) = cvt2h(v2);
                *(u32*)(vdst + (a * 6 + 3) * VS_PLANE) = cvt2h(v3);
                *(u32*)(vdst + (a * 6 + 4) * VS_PLANE) = cvt2h(v4);
                *(u32*)(vdst + (a * 6 + 5) * VS_PLANE) = cvt2h(v5);
            }
        }
        __syncthreads();
    }
    // V_s finalized for ALL warps.

    // ====== phase 1: GEMM + output transform (no block barriers) ======
    const int wid = tid >> 5, lane = tid & 31;
    const int g = lane >> 2, t4 = lane & 3;
    const int warpN = wid * 8;                // 8 co-warps x 8 cols

    const u32 wbuf = sb0 + OVL_OFF + (u32)wid * WBUF_WARP;
    const __half* wgbase = g_W + warpN * 64;

    // per-warp W fill: 8 co rows x 64 k halfs into the given stage
    auto wfill2 = [&](const __half* wp, u32 dst) {
#pragma unroll
        for (int i = 0; i < 2; i++) {
            int t = lane + i * 32;            // 0..63 tasks of 16 B
            int r = t >> 3, c = t & 7;
            cp16(dst + (u32)(r * 144 + c * 16), wp + r * 64 + c * 8);
        }
        asm volatile("cp.async.commit_group;" ::: "memory");
    };

    // A ldmatrix lane offset (16 rows per V plane)
    const u32 aLane = sb0 + (u32)((lane & 15) * 144 + (lane >> 4) * 16);
    // B ldmatrix.x4 lane offset: 8-lane groups -> 4 k-col matrices
    const u32 wLane = wbuf + (u32)((lane & 7) * 144 + (lane >> 3) * 16);

    float accY[4][4][4];                      // [elem][x][y]
#pragma unroll
    for (int e = 0; e < 4; e++)
#pragma unroll
        for (int xx = 0; xx < 4; xx++)
#pragma unroll
            for (int yy = 0; yy < 4; yy++) accY[e][xx][yy] = 0.0f;

    // initial fills: plane (a=0,b=0)=0 -> stage 0; plane (1,0)=6 -> stage 1
    wfill2(wgbase,            wbuf);
    wfill2(wgbase + 6 * 4096, wbuf + WBUF_ST);

    for (int b = 0; b < 6; b++) {
        const int bn = (b == 5) ? 0 : b + 1;            // wrap fills are harmless
        const __half* wpb = wgbase + b * 4096;
        const __half* wpn = wgbase + bn * 4096;
        const u32 aB = aLane + (u32)(b * VS_PLANE);

        float Z[4][4];
#pragma unroll
        for (int e = 0; e < 4; e++)
#pragma unroll
            for (int xx = 0; xx < 4; xx++) Z[e][xx] = 0.0f;

        float pv[4];                          // deferred d (a=1 / a=3)

#pragma unroll
        for (int a = 0; a < 6; a++) {
            // prefetch plane idx+2 into stage (a+2)%3 (all compile-time)
            if (a <= 3) wfill2(wpb + (a + 2) * 6 * 4096,
                               wbuf + (u32)(((a + 2) % 3) * WBUF_ST));
            else        wfill2(wpn + (a - 4) * 6 * 4096,
                               wbuf + (u32)(((a + 2) % 3) * WBUF_ST));
            asm volatile("cp.async.wait_group 2;" ::: "memory");
            __syncwarp();

            const u32 abase = aB + (u32)(a * 6 * VS_PLANE);
            const u32 wbase = wLane + (u32)((a % 3) * WBUF_ST);

            // B: all 4 k-chunks via 2 ldmx4
            u32 bw[8];
            ldmx4(bw, wbase);
            ldmx4(bw + 4, wbase + 64);

            // two independent 2-deep HMMA chains
            float dA[4] = {0, 0, 0, 0};
            float dB[4] = {0, 0, 0, 0};
            {
                u32 av[4];
                ldmx4(av, abase);       mma16f(dA, av, bw);
                ldmx4(av, abase + 32);  mma16f(dA, av, bw + 2);
                ldmx4(av, abase + 64);  mma16f(dB, av, bw + 4);
                ldmx4(av, abase + 96);  mma16f(dB, av, bw + 6);
            }

            // fold M_ab into Z with AT column a (compile-time a, butterflies)
#pragma unroll
            for (int r = 0; r < 4; r++) {
                float dd = dA[r] + dB[r];
                if (a == 0) {
                    Z[r][0] += dd;
                } else if (a == 1 || a == 3) {
                    pv[r] = dd;               // defer to butterfly
                } else if (a == 2) {
                    float s = pv[r] + dd;
                    float t = pv[r] - dd;
                    Z[r][0] += s; Z[r][2] += s;
                    Z[r][1] += t; Z[r][3] += t;
                } else if (a == 4) {
                    float s = pv[r] + dd;
                    float t = pv[r] - dd;
                    Z[r][0] += s;             Z[r][2] += 4.0f * s;
                    Z[r][1] += 2.0f * t;      Z[r][3] += 8.0f * t;
                } else {
                    Z[r][3] += dd;
                }
            }
        }

        // fold Z into Y with AT column b
        float c0, c1, c2c, c3;
        switch (b) {
            case 0:  c0 = 1; c1 = 0;  c2c = 0; c3 = 0;  break;
            case 1:  c0 = 1; c1 = 1;  c2c = 1; c3 = 1;  break;
            case 2:  c0 = 1; c1 = -1; c2c = 1; c3 = -1; break;
            case 3:  c0 = 1; c1 = 2;  c2c = 4; c3 = 8;  break;
            case 4:  c0 = 1; c1 = -2; c2c = 4; c3 = -8; break;
            default: c0 = 0; c1 = 0;  c2c = 0; c3 = 1;  break;
        }
#pragma unroll
        for (int e = 0; e < 4; e++)
#pragma unroll
            for (int xx = 0; xx < 4; xx++) {
                float z = Z[e][xx];
                accY[e][xx][0] += z * c0;
                accY[e][xx][1] += z * c1;
                accY[e][xx][2] += z * c2c;
                accY[e][xx][3] += z * c3;
            }
    }

    // ---- epilogue: bias + direct y stores ----
#pragma unroll
    for (int e = 0; e < 4; e++) {
        int co = warpN + 2 * t4 + (e & 1);
        int mrow = g + (e >> 1) * 8;          // 0..15
        float bv = __ldg(&bias[co]);
        int m = m0 + mrow;
        int qq = m & 31;
        float* yb = y + (((size_t)(n * 64 + co) * 128) + p * 4) * 128 + qq * 4;
#pragma unroll
        for (int xx = 0; xx < 4; xx++) {
            float4 st = make_float4(accY[e][xx][0] + bv, accY[e][xx][1] + bv,
                                    accY[e][xx][2] + bv, accY[e][xx][3] + bv);
            *(float4*)(yb + xx * 128) = st;
        }
    }
}

// ---------------------------------------------------------------------------
extern "C" void kernel_launch(void* const* d_in, const int* in_sizes, int n_in,
                              void* d_out, int out_size) {
    const float* x = (const float*)d_in[0];   // (16, 64, 128, 128) f32
    const float* w = (const float*)d_in[1];   // (64, 64, 6, 6) f32
    const float* b = (const float*)d_in[2];   // (64,) f32
    float* y = (float*)d_out;                 // (16, 64, 128, 128) f32

    cudaFuncSetAttribute(mega_kernel, cudaFuncAttributeMaxDynamicSharedMemorySize,
                         GSM_TOTAL);

    wt_kernel<<<(NAB * 64 * 64 + 255) / 256, 256>>>(w);
    mega_kernel<<<1024, 256, GSM_TOTAL>>>(x, b, y);
}